// round 5
// baseline (speedup 1.0000x reference)
#include <cuda_runtime.h>

#define NBATCH 16
#define NPTS0  4096
#define FULLMASK 0xffffffffu

// ---------------- device scratch (no allocations allowed) ------------------
__device__ float4 g_xyz0[NBATCH * NPTS0];      // x,y,z,|p|^2
__device__ float  g_pts0[NBATCH * NPTS0 * 9];
__device__ float4 g_nx1[NBATCH * 1024];
__device__ float  g_f1 [NBATCH * 1024 * 64];
__device__ float4 g_nx2[NBATCH * 256];
__device__ float  g_f2 [NBATCH * 256 * 128];
__device__ float4 g_nx3[NBATCH * 64];
__device__ float  g_f3 [NBATCH * 64 * 256];
__device__ float4 g_nx4[NBATCH * 16];
__device__ float  g_f4 [NBATCH * 16 * 512];
__device__ int    g_prog[NBATCH];              // fps1 progress per batch

// ---------------- d_out offsets (float elements) ----------------------------
#define O1 0        // [16,3,4096]
#define O2 196608   // [16,3,1024]
#define O3 245760   // [16,3,256]
#define O4 258048   // [16,3,64]
#define O5 261120   // [16,3,16]
#define O6 261888   // [16,64,1024]
#define O7 1310464  // [16,128,256]
#define O8 1834752  // [16,256,64]
#define O9 2096896  // [16,512,16]

__device__ __forceinline__ float sq3(float a, float b, float c) {
    return __fadd_rn(__fadd_rn(__fmul_rn(a, a), __fmul_rn(b, b)), __fmul_rn(c, c));
}

// ---- packed f32x2 helpers (lanewise rn == __fadd_rn/__fmul_rn, bit-exact) --
__device__ __forceinline__ unsigned long long pk2(float lo, float hi) {
    unsigned long long r;
    asm("mov.b64 %0, {%1, %2};" : "=l"(r) : "f"(lo), "f"(hi));
    return r;
}
__device__ __forceinline__ void upk2(float& lo, float& hi, unsigned long long v) {
    asm("mov.b64 {%0, %1}, %2;" : "=f"(lo), "=f"(hi) : "l"(v));
}
__device__ __forceinline__ unsigned long long add2(unsigned long long a, unsigned long long b) {
    unsigned long long r;
    asm("add.rn.f32x2 %0, %1, %2;" : "=l"(r) : "l"(a), "l"(b));
    return r;
}
__device__ __forceinline__ unsigned long long mul2(unsigned long long a, unsigned long long b) {
    unsigned long long r;
    asm("mul.rn.f32x2 %0, %1, %2;" : "=l"(r) : "l"(a), "l"(b));
    return r;
}

// ---- acquire/release + volatile vector load --------------------------------
__device__ __forceinline__ int ld_acquire(const int* p) {
    int v;
    asm volatile("ld.global.acquire.gpu.b32 %0, [%1];" : "=r"(v) : "l"(p));
    return v;
}
__device__ __forceinline__ void st_release(int* p, int v) {
    asm volatile("st.global.release.gpu.b32 [%0], %1;" :: "l"(p), "r"(v));
}
__device__ __forceinline__ float4 ldv4(const float4* p) {
    float4 v;
    asm volatile("ld.volatile.global.v4.f32 {%0,%1,%2,%3}, [%4];"
                 : "=f"(v.x), "=f"(v.y), "=f"(v.z), "=f"(v.w) : "l"(p));
    return v;
}

// ---------------------------------------------------------------------------
// Transpose [B,9,N] -> point-major scratch (+ |p|^2), emits out1, resets prog.
// ---------------------------------------------------------------------------
__global__ void k_transpose(const float* __restrict__ in, float* __restrict__ out1) {
    if (blockIdx.x == 0 && threadIdx.x < NBATCH) g_prog[threadIdx.x] = 0;
    int i = blockIdx.x * blockDim.x + threadIdx.x;
    if (i >= NBATCH * NPTS0) return;
    int b = i >> 12;
    int n = i & (NPTS0 - 1);
    const float* src = in + (size_t)b * 9 * NPTS0;
    float v[9];
#pragma unroll
    for (int c = 0; c < 9; c++) v[c] = src[c * NPTS0 + n];
#pragma unroll
    for (int c = 0; c < 9; c++) g_pts0[(size_t)i * 9 + c] = v[c];
    g_xyz0[i] = make_float4(v[0], v[1], v[2], sq3(v[0], v[1], v[2]));
#pragma unroll
    for (int c = 0; c < 3; c++) out1[((size_t)b * 3 + c) * NPTS0 + n] = v[c];
}

// ---------------------------------------------------------------------------
// FPS body: coords in SoA dynamic smem, dist in regs, packed f32x2 updates.
// T = 256 (8 warps). One barrier per iteration. PROG: release per-center
// progress (producer). WAITFULL: spin until producer finished (consumer fps).
// ---------------------------------------------------------------------------
template <int NPf, int Sf, bool PROG, bool WAITFULL>
__device__ void fps_smem(const float4* __restrict__ src, float4* __restrict__ nx,
                         float* __restrict__ dout, int b, int tid, float* fsm) {
    constexpr int T = 256;
    constexpr int NW = 8;
    constexpr int PPT = (NPf + T - 1) / T;
    constexpr bool GUARD = (NPf % T) != 0;
    float* sx = fsm;
    float* sy = fsm + NPf;
    float* sz = fsm + 2 * NPf;
    __shared__ unsigned long long skey[2][NW];
    int lane = tid & 31, wd = tid >> 5;

    if (WAITFULL) {
        if (tid == 0) {
            while (ld_acquire(&g_prog[b]) < NPf) __nanosleep(256);
        }
        __syncthreads();
    }

    const float4* psrc = src + (size_t)b * NPf;
    float dist[PPT];
#pragma unroll
    for (int j = 0; j < PPT; j++) {
        int p = tid + j * T;
        dist[j] = 1e10f;
        if (!GUARD || p < NPf) {
            float4 v = WAITFULL ? ldv4(&psrc[p]) : psrc[p];
            sx[p] = v.x; sy[p] = v.y; sz[p] = v.z;
        }
    }
    __syncthreads();

    int far = 0;
    for (int s = 0; s < Sf; s++) {
        float fx = sx[far], fy = sy[far], fz = sz[far];
        if (tid == 0) {
            nx[(size_t)b * Sf + s] = make_float4(fx, fy, fz, sq3(fx, fy, fz));
            dout[((size_t)b * 3 + 0) * Sf + s] = fx;
            dout[((size_t)b * 3 + 1) * Sf + s] = fy;
            dout[((size_t)b * 3 + 2) * Sf + s] = fz;
            if (PROG) st_release(&g_prog[b], s + 1);
        }
        unsigned bb = 0u, bi = 0xffffffffu;
        unsigned long long nfx = pk2(-fx, -fx), nfy = pk2(-fy, -fy), nfz = pk2(-fz, -fz);
#pragma unroll
        for (int j = 0; j + 1 < PPT; j += 2) {
            int p0 = tid + j * T, p1 = p0 + T;
            unsigned long long X = pk2(sx[p0], sx[p1]);
            unsigned long long Y = pk2(sy[p0], sy[p1]);
            unsigned long long Z = pk2(sz[p0], sz[p1]);
            unsigned long long dx = add2(X, nfx);
            unsigned long long dy = add2(Y, nfy);
            unsigned long long dz = add2(Z, nfz);
            unsigned long long ss = add2(add2(mul2(dx, dx), mul2(dy, dy)), mul2(dz, dz));
            float d0, d1; upk2(d0, d1, ss);
            float n0 = fminf(dist[j], d0);     dist[j] = n0;
            float n1 = fminf(dist[j + 1], d1); dist[j + 1] = n1;
            unsigned u0 = __float_as_uint(n0), u1 = __float_as_uint(n1);
            if (u0 > bb || (u0 == bb && (unsigned)p0 < bi)) { bb = u0; bi = (unsigned)p0; }
            if (u1 > bb || (u1 == bb && (unsigned)p1 < bi)) { bb = u1; bi = (unsigned)p1; }
        }
        if constexpr (PPT & 1) {
            constexpr int j = PPT - 1;
            int p = tid + j * T;
            if (!GUARD || p < NPf) {
                float dxs = __fadd_rn(sx[p], -fx);
                float dys = __fadd_rn(sy[p], -fy);
                float dzs = __fadd_rn(sz[p], -fz);
                float d = sq3(dxs, dys, dzs);
                float nd = fminf(dist[j], d);
                dist[j] = nd;
                unsigned ub = __float_as_uint(nd);
                if (ub > bb || (ub == bb && (unsigned)p < bi)) { bb = ub; bi = (unsigned)p; }
            }
        }
        unsigned mb = __reduce_max_sync(FULLMASK, bb);
        unsigned cand = (bb == mb) ? bi : 0xffffffffu;
        unsigned mi = __reduce_min_sync(FULLMASK, cand);
        if (lane == 0)
            skey[s & 1][wd] = ((unsigned long long)mb << 32) |
                              (unsigned long long)(0xffffffffu - mi);
        __syncthreads();
        unsigned long long best = skey[s & 1][0];
#pragma unroll
        for (int i = 1; i < NW; i++) {
            unsigned long long o = skey[s & 1][i];
            if (o > best) best = o;
        }
        far = (int)(0xffffffffu - (unsigned)(best & 0xffffffffu));
    }
}

// ---------------------------------------------------------------------------
// MLP stages (as R4): smem-staged weights, lane=k, OB reg accumulators.
// ---------------------------------------------------------------------------
template <int CIa, int CIp, int CO, int PI, int PO>
__device__ __forceinline__ void mlp_mid(const float* __restrict__ fin,
                                        float* __restrict__ fo,
                                        float* __restrict__ wsm,
                                        const float* __restrict__ W,
                                        const float* __restrict__ Bv, int tid) {
    constexpr int OB = CO / 8;
    int lane = tid & 31;
    int obase = (tid >> 5) * OB;
    float acc[OB];
#pragma unroll
    for (int j = 0; j < OB; j++) acc[j] = __ldg(Bv + obase + j);
    const float* frow = fin + lane * PI;
    for (int ci0 = 0; ci0 < CIp; ci0 += 16) {
        __syncthreads();
        for (int e = tid; e < CO * 16; e += 256) {
            int o = e >> 4, g = e & 15;
            int ci = ci0 + g;
            wsm[o * 20 + g] = (ci < CIa) ? __ldg(W + o * CIa + ci) : 0.0f;
        }
        __syncthreads();
        int gmax = (CIp - ci0 < 16) ? (CIp - ci0) : 16;
        for (int g = 0; g < gmax; g += 4) {
            float4 f4 = *(const float4*)(frow + ci0 + g);
            const float* wb = wsm + obase * 20 + g;
#pragma unroll
            for (int j = 0; j < OB; j++) {
                float4 w4 = *(const float4*)(wb + j * 20);
                acc[j] = fmaf(w4.x, f4.x, acc[j]);
                acc[j] = fmaf(w4.y, f4.y, acc[j]);
                acc[j] = fmaf(w4.z, f4.z, acc[j]);
                acc[j] = fmaf(w4.w, f4.w, acc[j]);
            }
        }
    }
    float* orow = fo + lane * PO + obase;
#pragma unroll
    for (int j = 0; j < OB; j++) orow[j] = fmaxf(acc[j], 0.0f);
}

template <int CIa, int CIp, int CO, int PI>
__device__ __forceinline__ void mlp_last(const float* __restrict__ fin,
                                         float* __restrict__ wsm,
                                         const float* __restrict__ W,
                                         const float* __restrict__ Bv,
                                         float* __restrict__ foutp,
                                         float* __restrict__ doutp,
                                         int S_, int tid) {
    constexpr int OB = CO / 8;
    int lane = tid & 31;
    int obase = (tid >> 5) * OB;
    float acc[OB];
#pragma unroll
    for (int j = 0; j < OB; j++) acc[j] = __ldg(Bv + obase + j);
    const float* frow = fin + lane * PI;
    for (int ci0 = 0; ci0 < CIp; ci0 += 16) {
        __syncthreads();
        for (int e = tid; e < CO * 16; e += 256) {
            int o = e >> 4, g = e & 15;
            int ci = ci0 + g;
            wsm[o * 20 + g] = (ci < CIa) ? __ldg(W + o * CIa + ci) : 0.0f;
        }
        __syncthreads();
        int gmax = (CIp - ci0 < 16) ? (CIp - ci0) : 16;
        for (int g = 0; g < gmax; g += 4) {
            float4 f4 = *(const float4*)(frow + ci0 + g);
            const float* wb = wsm + obase * 20 + g;
#pragma unroll
            for (int j = 0; j < OB; j++) {
                float4 w4 = *(const float4*)(wb + j * 20);
                acc[j] = fmaf(w4.x, f4.x, acc[j]);
                acc[j] = fmaf(w4.y, f4.y, acc[j]);
                acc[j] = fmaf(w4.z, f4.z, acc[j]);
                acc[j] = fmaf(w4.w, f4.w, acc[j]);
            }
        }
    }
#pragma unroll
    for (int j = 0; j < OB; j++) {
        float m = fmaxf(acc[j], 0.0f);
#pragma unroll
        for (int off = 16; off > 0; off >>= 1)
            m = fmaxf(m, __shfl_xor_sync(FULLMASK, m, off));
        if (lane == 0) {
            int o = obase + j;
            foutp[o] = m;
            doutp[(size_t)o * S_] = m;
        }
    }
}

// ---------------------------------------------------------------------------
// Fused SA layer.
//  SPIN=true (layer 1): blocks [0,16) run THIS layer's FPS (producer, with
//  progress release), blocks [16,32) run next layer's FPS (waits for all
//  centers), remaining blocks are consumers that spin for their center.
//  SPIN=false: optional blocks [0,16) run next layer's FPS (inputs complete).
// ---------------------------------------------------------------------------
template <int NP, int S, int D, int C1, int C2, int C3, int CINp, int PA,
          int NWQ, int SOUT, bool SPIN>
__global__ __launch_bounds__(256, 4) void k_sa(const float4* __restrict__ xyz4,
                                               const float* __restrict__ pts,
                                               const float4* __restrict__ cxyz,
                                               const float* __restrict__ W1, const float* __restrict__ B1,
                                               const float* __restrict__ W2, const float* __restrict__ B2,
                                               const float* __restrict__ W3, const float* __restrict__ B3,
                                               float* __restrict__ fout,
                                               float* __restrict__ dout, float r2,
                                               float4* __restrict__ nxout,
                                               float* __restrict__ dout2,
                                               float4* __restrict__ nx_this,
                                               float* __restrict__ dout_this) {
    constexpr int CIN = D + 3;
    extern __shared__ float smdyn[];
    int bid = blockIdx.x;
    int tid = threadIdx.x;

    int b, s;
    if constexpr (SPIN) {
        if (bid < NBATCH) {          // producer FPS for THIS layer
            fps_smem<NP, S, true, false>(xyz4, nx_this, dout_this, bid, tid, smdyn);
            return;
        }
        if (bid < 2 * NBATCH) {      // FPS for next layer (waits for producer)
            fps_smem<S, SOUT, false, true>(cxyz, nxout, dout2, bid - NBATCH, tid, smdyn);
            return;
        }
        int i = bid - 2 * NBATCH;
        b = i & (NBATCH - 1);        // interleave so resident blocks need early s
        s = i >> 4;
    } else {
        if constexpr (SOUT > 0) {
            if (bid < NBATCH) {
                fps_smem<S, SOUT, false, false>(cxyz, nxout, dout2, bid, tid, smdyn);
                return;
            }
            bid -= NBATCH;
        }
        b = bid / S;
        s = bid - b * S;
    }

    float* bufA = smdyn;            // [32, PA]
    float* bufB = smdyn + 32 * PA;  // [32, PA]
    float* wsm  = smdyn + 64 * PA;  // [COmax, 20]
    __shared__ int hits[8][32];
    __shared__ int cnts[8];
    __shared__ int nidx[32];
    __shared__ float cen[3];

    int lane = tid & 31, wd = tid >> 5;

    if constexpr (SPIN) {
        if (tid == 0) {
            while (ld_acquire(&g_prog[b]) <= s) __nanosleep(64);
        }
        __syncthreads();
    }

    float4 cv = SPIN ? ldv4(&cxyz[(size_t)b * S + s])     // L1-bypass: fresh data
                     : __ldg(&cxyz[(size_t)b * S + s]);
    float cx = cv.x, cy = cv.y, cz = cv.z, smc = cv.w;
    if (tid == 0) { cen[0] = cx; cen[1] = cy; cen[2] = cz; }

    // ---- ball query: NWQ warps scan disjoint ordered chunks ----
    if (wd < NWQ) {
        constexpr int CHUNK = NP / NWQ;
        const float4* px = xyz4 + (size_t)b * NP;
        int cnt = 0;
        for (int base = wd * CHUNK; base < (wd + 1) * CHUNK; base += 32) {
            int p = base + lane;
            float4 v = __ldg(&px[p]);
            float dot = __fadd_rn(__fadd_rn(__fmul_rn(cx, v.x), __fmul_rn(cy, v.y)),
                                  __fmul_rn(cz, v.z));
            float sq = __fadd_rn(__fadd_rn(smc, v.w), -__fmul_rn(2.0f, dot));
            bool hit = !(sq > r2);
            unsigned m = __ballot_sync(FULLMASK, hit);
            if (hit) {
                int pos = cnt + __popc(m & ((1u << lane) - 1u));
                if (pos < 32) hits[wd][pos] = p;
            }
            cnt += __popc(m);
            if (cnt >= 32) break;
        }
        if (lane == 0) cnts[wd] = (cnt < 32) ? cnt : 32;
    }
    __syncthreads();
    // ---- merge (warp 0), ascending index order; pad with first hit ----
    if (tid < 32) {
        int total = 0;
#pragma unroll
        for (int w2 = 0; w2 < NWQ; w2++) {
            int c = cnts[w2];
            int take = (c < 32 - total) ? c : (32 - total);
            if (lane < take) nidx[total + lane] = hits[w2][lane];
            total += take;
        }
        __syncwarp();
        int i0 = nidx[0];
        if (lane >= total) nidx[lane] = i0;
    }
    __syncthreads();

    // ---- gather: [rel_xyz(3), pts(D), zero-pad] into bufA ----
    float c0 = cen[0], c1 = cen[1], c2 = cen[2];
    for (int e = tid; e < 32 * CINp; e += 256) {
        int k = e / CINp;
        int c = e - k * CINp;
        int p = nidx[k];
        float v = 0.0f;
        if (c < 3) {
            float cc = (c == 0) ? c0 : (c == 1) ? c1 : c2;
            const float* xf = (const float*)(xyz4 + (size_t)b * NP + p);
            v = __fadd_rn(xf[c], -cc);
        } else if (c < CIN) {
            v = pts[((size_t)b * NP + p) * D + (c - 3)];
        }
        bufA[k * PA + c] = v;
    }
    // (stage-1's leading __syncthreads covers gather completion)

    mlp_mid<CIN, CINp, C1, PA, PA>(bufA, bufB, wsm, W1, B1, tid);
    mlp_mid<C1, C1, C2, PA, PA>(bufB, bufA, wsm, W2, B2, tid);
    mlp_last<C2, C2, C3, PA>(bufA, wsm, W3, B3,
                             fout + ((size_t)b * S + s) * C3,
                             dout + (size_t)b * C3 * S + s, S, tid);
}

// ---------------------------------------------------------------------------
extern "C" void kernel_launch(void* const* d_in, const int* in_sizes, int n_in,
                              void* d_out, int out_size) {
    const float* xin = (const float*)d_in[0];
    const float* w1a = (const float*)d_in[1];  const float* b1a = (const float*)d_in[2];
    const float* w1b = (const float*)d_in[3];  const float* b1b = (const float*)d_in[4];
    const float* w1c = (const float*)d_in[5];  const float* b1c = (const float*)d_in[6];
    const float* w2a = (const float*)d_in[7];  const float* b2a = (const float*)d_in[8];
    const float* w2b = (const float*)d_in[9];  const float* b2b = (const float*)d_in[10];
    const float* w2c = (const float*)d_in[11]; const float* b2c = (const float*)d_in[12];
    const float* w3a = (const float*)d_in[13]; const float* b3a = (const float*)d_in[14];
    const float* w3b = (const float*)d_in[15]; const float* b3b = (const float*)d_in[16];
    const float* w3c = (const float*)d_in[17]; const float* b3c = (const float*)d_in[18];
    const float* w4a = (const float*)d_in[19]; const float* b4a = (const float*)d_in[20];
    const float* w4b = (const float*)d_in[21]; const float* b4b = (const float*)d_in[22];
    const float* w4c = (const float*)d_in[23]; const float* b4c = (const float*)d_in[24];
    float* out = (float*)d_out;

    float4 *p_xyz0, *p_nx1, *p_nx2, *p_nx3, *p_nx4;
    float *p_pts0, *p_f1, *p_f2, *p_f3, *p_f4;
    cudaGetSymbolAddress((void**)&p_xyz0, g_xyz0);
    cudaGetSymbolAddress((void**)&p_pts0, g_pts0);
    cudaGetSymbolAddress((void**)&p_nx1, g_nx1);
    cudaGetSymbolAddress((void**)&p_f1, g_f1);
    cudaGetSymbolAddress((void**)&p_nx2, g_nx2);
    cudaGetSymbolAddress((void**)&p_f2, g_f2);
    cudaGetSymbolAddress((void**)&p_nx3, g_nx3);
    cudaGetSymbolAddress((void**)&p_f3, g_f3);
    cudaGetSymbolAddress((void**)&p_nx4, g_nx4);
    cudaGetSymbolAddress((void**)&p_f4, g_f4);

    float r2_1 = (float)(0.1 * 0.1);
    float r2_2 = (float)(0.2 * 0.2);
    float r2_3 = (float)(0.4 * 0.4);
    float r2_4 = (float)(0.8 * 0.8);

    // dynamic smem per launch = max(sa usage, fps SoA usage 3*NP*4)
    const int SM1 = 3 * NPTS0 * 4;              // 49152 (sa1 path uses 14336)
    const int SM2 = (64 * 68 + 128 * 20) * 4;   // 27648 (fps3: 12288)
    const int SM3 = (64 * 132 + 256 * 20) * 4;  // 54272 (fps4: 3072)
    const int SM4 = (64 * 260 + 512 * 20) * 4;  // 107520

    cudaFuncSetAttribute(k_sa<4096, 1024, 9, 32, 32, 64, 12, 36, 8, 256, true>,
                         cudaFuncAttributeMaxDynamicSharedMemorySize, SM1);
    cudaFuncSetAttribute(k_sa<256, 64, 128, 128, 128, 256, 132, 132, 8, 16, false>,
                         cudaFuncAttributeMaxDynamicSharedMemorySize, SM3);
    cudaFuncSetAttribute(k_sa<64, 16, 256, 256, 256, 512, 260, 260, 2, 0, false>,
                         cudaFuncAttributeMaxDynamicSharedMemorySize, SM4);

    // stage 0: transpose + output 1 + prog reset
    k_transpose<<<(NBATCH * NPTS0 + 255) / 256, 256>>>(xin, out + O1);

    // layer 1 SA with embedded fps1 (producer) + fps2 (next layer)
    k_sa<4096, 1024, 9, 32, 32, 64, 12, 36, 8, 256, true>
        <<<NBATCH * 1024 + 2 * NBATCH, 256, SM1>>>(
        p_xyz0, p_pts0, p_nx1, w1a, b1a, w1b, b1b, w1c, b1c,
        p_f1, out + O6, r2_1, p_nx2, out + O3, p_nx1, out + O2);

    // layer 2 SA (+ embedded fps3 -> nx3, out O4)
    k_sa<1024, 256, 64, 64, 64, 128, 68, 68, 8, 64, false>
        <<<NBATCH * 256 + NBATCH, 256, SM2>>>(
        p_nx1, p_f1, p_nx2, w2a, b2a, w2b, b2b, w2c, b2c,
        p_f2, out + O7, r2_2, p_nx3, out + O4, nullptr, nullptr);

    // layer 3 SA (+ embedded fps4 -> nx4, out O5)
    k_sa<256, 64, 128, 128, 128, 256, 132, 132, 8, 16, false>
        <<<NBATCH * 64 + NBATCH, 256, SM3>>>(
        p_nx2, p_f2, p_nx3, w3a, b3a, w3b, b3b, w3c, b3c,
        p_f3, out + O8, r2_3, p_nx4, out + O5, nullptr, nullptr);

    // layer 4 SA (no tail)
    k_sa<64, 16, 256, 256, 256, 512, 260, 260, 2, 0, false>
        <<<NBATCH * 16, 256, SM4>>>(
        p_nx3, p_f3, p_nx4, w4a, b4a, w4b, b4b, w4c, b4c,
        p_f4, out + O9, r2_4, nullptr, nullptr, nullptr, nullptr);
}

// round 6
// speedup vs baseline: 1.1749x; 1.1749x over previous
#include <cuda_runtime.h>

#define NBATCH 16
#define NPTS0  4096
#define FULLMASK 0xffffffffu

// ---------------- device scratch (no allocations allowed) ------------------
__device__ float4 g_xyz0[NBATCH * NPTS0];      // x,y,z,|p|^2
__device__ float  g_pts0[NBATCH * NPTS0 * 9];
__device__ float4 g_nx1[NBATCH * 1024];
__device__ float  g_f1 [NBATCH * 1024 * 64];
__device__ float4 g_nx2[NBATCH * 256];
__device__ float  g_f2 [NBATCH * 256 * 128];
__device__ float4 g_nx3[NBATCH * 64];
__device__ float  g_f3 [NBATCH * 64 * 256];
__device__ float4 g_nx4[NBATCH * 16];
__device__ float  g_f4 [NBATCH * 16 * 512];

// ---------------- d_out offsets (float elements) ----------------------------
#define O1 0        // [16,3,4096]
#define O2 196608   // [16,3,1024]
#define O3 245760   // [16,3,256]
#define O4 258048   // [16,3,64]
#define O5 261120   // [16,3,16]
#define O6 261888   // [16,64,1024]
#define O7 1310464  // [16,128,256]
#define O8 1834752  // [16,256,64]
#define O9 2096896  // [16,512,16]

__device__ __forceinline__ float sq3(float a, float b, float c) {
    return __fadd_rn(__fadd_rn(__fmul_rn(a, a), __fmul_rn(b, b)), __fmul_rn(c, c));
}

// ---- packed f32x2 helpers (lanewise rn == __fadd_rn/__fmul_rn, bit-exact) --
__device__ __forceinline__ unsigned long long pk2(float lo, float hi) {
    unsigned long long r;
    asm("mov.b64 %0, {%1, %2};" : "=l"(r) : "f"(lo), "f"(hi));
    return r;
}
__device__ __forceinline__ void upk2(float& lo, float& hi, unsigned long long v) {
    asm("mov.b64 {%0, %1}, %2;" : "=f"(lo), "=f"(hi) : "l"(v));
}
__device__ __forceinline__ unsigned long long add2(unsigned long long a, unsigned long long b) {
    unsigned long long r;
    asm("add.rn.f32x2 %0, %1, %2;" : "=l"(r) : "l"(a), "l"(b));
    return r;
}
__device__ __forceinline__ unsigned long long mul2(unsigned long long a, unsigned long long b) {
    unsigned long long r;
    asm("mul.rn.f32x2 %0, %1, %2;" : "=l"(r) : "l"(a), "l"(b));
    return r;
}

// ---------------------------------------------------------------------------
// Transpose [B,9,N] -> point-major scratch (+ |p|^2), emits out1.
// ---------------------------------------------------------------------------
__global__ void k_transpose(const float* __restrict__ in, float* __restrict__ out1) {
    int i = blockIdx.x * blockDim.x + threadIdx.x;
    if (i >= NBATCH * NPTS0) return;
    int b = i >> 12;
    int n = i & (NPTS0 - 1);
    const float* src = in + (size_t)b * 9 * NPTS0;
    float v[9];
#pragma unroll
    for (int c = 0; c < 9; c++) v[c] = src[c * NPTS0 + n];
#pragma unroll
    for (int c = 0; c < 9; c++) g_pts0[(size_t)i * 9 + c] = v[c];
    g_xyz0[i] = make_float4(v[0], v[1], v[2], sq3(v[0], v[1], v[2]));
#pragma unroll
    for (int c = 0; c < 3; c++) out1[((size_t)b * 3 + c) * NPTS0 + n] = v[c];
}

// ---------------------------------------------------------------------------
// FPS body: coords in SoA dynamic smem, dist in regs, packed f32x2 updates.
// One barrier per iteration; warp redux.sync argmax -> u64 key in smem ->
// every thread redundantly reduces NW keys in registers.
// ---------------------------------------------------------------------------
template <int NPf, int Sf, int T>
__device__ void fps_soa(const float4* __restrict__ src, float4* __restrict__ nx,
                        float* __restrict__ dout, int b, int tid, float* fsm) {
    constexpr int NW = T / 32;
    constexpr int PPT = (NPf + T - 1) / T;
    constexpr bool GUARD = (NPf % T) != 0;
    float* sx = fsm;
    float* sy = fsm + NPf;
    float* sz = fsm + 2 * NPf;
    __shared__ unsigned long long skey[2][16];
    int lane = tid & 31, wd = tid >> 5;

    const float4* psrc = src + (size_t)b * NPf;
    float dist[PPT];
#pragma unroll
    for (int j = 0; j < PPT; j++) {
        int p = tid + j * T;
        dist[j] = 1e10f;
        if (!GUARD || p < NPf) {
            float4 v = psrc[p];
            sx[p] = v.x; sy[p] = v.y; sz[p] = v.z;
        }
    }
    __syncthreads();

    int far = 0;
    for (int s = 0; s < Sf; s++) {
        float fx = sx[far], fy = sy[far], fz = sz[far];
        if (tid == 0) {
            nx[(size_t)b * Sf + s] = make_float4(fx, fy, fz, sq3(fx, fy, fz));
            dout[((size_t)b * 3 + 0) * Sf + s] = fx;
            dout[((size_t)b * 3 + 1) * Sf + s] = fy;
            dout[((size_t)b * 3 + 2) * Sf + s] = fz;
        }
        unsigned bb = 0u, bi = 0xffffffffu;
        unsigned long long nfx = pk2(-fx, -fx), nfy = pk2(-fy, -fy), nfz = pk2(-fz, -fz);
#pragma unroll
        for (int j = 0; j + 1 < PPT; j += 2) {   // only instantiated when NPf >= 2T
            int p0 = tid + j * T, p1 = p0 + T;
            unsigned long long X = pk2(sx[p0], sx[p1]);
            unsigned long long Y = pk2(sy[p0], sy[p1]);
            unsigned long long Z = pk2(sz[p0], sz[p1]);
            unsigned long long dx = add2(X, nfx);
            unsigned long long dy = add2(Y, nfy);
            unsigned long long dz = add2(Z, nfz);
            unsigned long long ss = add2(add2(mul2(dx, dx), mul2(dy, dy)), mul2(dz, dz));
            float d0, d1; upk2(d0, d1, ss);
            float n0 = fminf(dist[j], d0);     dist[j] = n0;
            float n1 = fminf(dist[j + 1], d1); dist[j + 1] = n1;
            unsigned u0 = __float_as_uint(n0), u1 = __float_as_uint(n1);
            if (u0 > bb || (u0 == bb && (unsigned)p0 < bi)) { bb = u0; bi = (unsigned)p0; }
            if (u1 > bb || (u1 == bb && (unsigned)p1 < bi)) { bb = u1; bi = (unsigned)p1; }
        }
        if constexpr (PPT & 1) {
            constexpr int j = PPT - 1;
            int p = tid + j * T;
            if (!GUARD || p < NPf) {
                float dxs = __fadd_rn(sx[p], -fx);
                float dys = __fadd_rn(sy[p], -fy);
                float dzs = __fadd_rn(sz[p], -fz);
                float d = sq3(dxs, dys, dzs);
                float nd = fminf(dist[j], d);
                dist[j] = nd;
                unsigned ub = __float_as_uint(nd);
                if (ub > bb || (ub == bb && (unsigned)p < bi)) { bb = ub; bi = (unsigned)p; }
            }
        }
        unsigned mb = __reduce_max_sync(FULLMASK, bb);
        unsigned cand = (bb == mb) ? bi : 0xffffffffu;
        unsigned mi = __reduce_min_sync(FULLMASK, cand);
        if (lane == 0)
            skey[s & 1][wd] = ((unsigned long long)mb << 32) |
                              (unsigned long long)(0xffffffffu - mi);
        __syncthreads();
        unsigned long long best = skey[s & 1][0];
#pragma unroll
        for (int i = 1; i < NW; i++) {
            unsigned long long o = skey[s & 1][i];
            if (o > best) best = o;
        }
        far = (int)(0xffffffffu - (unsigned)(best & 0xffffffffu));
    }
}

template <int NPf, int Sf, int T>
__global__ __launch_bounds__(T) void k_fps(const float4* __restrict__ xyz,
                                           float4* __restrict__ nx,
                                           float* __restrict__ dout) {
    extern __shared__ float smdyn[];
    fps_soa<NPf, Sf, T>(xyz, nx, dout, blockIdx.x, threadIdx.x, smdyn);
}

// ---------------------------------------------------------------------------
// MLP stages: smem-staged weights (16-ci chunks, pitch 20), lane = neighbor k,
// each thread accumulates OB = CO/(NT/32) outputs in registers.
// ---------------------------------------------------------------------------
template <int CIa, int CIp, int CO, int PI, int PO, int NT>
__device__ __forceinline__ void mlp_mid(const float* __restrict__ fin,
                                        float* __restrict__ fo,
                                        float* __restrict__ wsm,
                                        const float* __restrict__ W,
                                        const float* __restrict__ Bv, int tid) {
    constexpr int OB = CO / (NT / 32);
    int lane = tid & 31;
    int obase = (tid >> 5) * OB;
    float acc[OB];
#pragma unroll
    for (int j = 0; j < OB; j++) acc[j] = __ldg(Bv + obase + j);
    const float* frow = fin + lane * PI;
    for (int ci0 = 0; ci0 < CIp; ci0 += 16) {
        __syncthreads();
        for (int e = tid; e < CO * 16; e += NT) {
            int o = e >> 4, g = e & 15;
            int ci = ci0 + g;
            wsm[o * 20 + g] = (ci < CIa) ? __ldg(W + o * CIa + ci) : 0.0f;
        }
        __syncthreads();
        int gmax = (CIp - ci0 < 16) ? (CIp - ci0) : 16;
        for (int g = 0; g < gmax; g += 4) {
            float4 f4 = *(const float4*)(frow + ci0 + g);
            const float* wb = wsm + obase * 20 + g;
#pragma unroll
            for (int j = 0; j < OB; j++) {
                float4 w4 = *(const float4*)(wb + j * 20);
                acc[j] = fmaf(w4.x, f4.x, acc[j]);
                acc[j] = fmaf(w4.y, f4.y, acc[j]);
                acc[j] = fmaf(w4.z, f4.z, acc[j]);
                acc[j] = fmaf(w4.w, f4.w, acc[j]);
            }
        }
    }
    float* orow = fo + lane * PO + obase;
#pragma unroll
    for (int j = 0; j < OB; j++) orow[j] = fmaxf(acc[j], 0.0f);
}

template <int CIa, int CIp, int CO, int PI, int NT>
__device__ __forceinline__ void mlp_last(const float* __restrict__ fin,
                                         float* __restrict__ wsm,
                                         const float* __restrict__ W,
                                         const float* __restrict__ Bv,
                                         float* __restrict__ foutp,
                                         float* __restrict__ doutp,
                                         int S_, int tid) {
    constexpr int OB = CO / (NT / 32);
    int lane = tid & 31;
    int obase = (tid >> 5) * OB;
    float acc[OB];
#pragma unroll
    for (int j = 0; j < OB; j++) acc[j] = __ldg(Bv + obase + j);
    const float* frow = fin + lane * PI;
    for (int ci0 = 0; ci0 < CIp; ci0 += 16) {
        __syncthreads();
        for (int e = tid; e < CO * 16; e += NT) {
            int o = e >> 4, g = e & 15;
            int ci = ci0 + g;
            wsm[o * 20 + g] = (ci < CIa) ? __ldg(W + o * CIa + ci) : 0.0f;
        }
        __syncthreads();
        int gmax = (CIp - ci0 < 16) ? (CIp - ci0) : 16;
        for (int g = 0; g < gmax; g += 4) {
            float4 f4 = *(const float4*)(frow + ci0 + g);
            const float* wb = wsm + obase * 20 + g;
#pragma unroll
            for (int j = 0; j < OB; j++) {
                float4 w4 = *(const float4*)(wb + j * 20);
                acc[j] = fmaf(w4.x, f4.x, acc[j]);
                acc[j] = fmaf(w4.y, f4.y, acc[j]);
                acc[j] = fmaf(w4.z, f4.z, acc[j]);
                acc[j] = fmaf(w4.w, f4.w, acc[j]);
            }
        }
    }
#pragma unroll
    for (int j = 0; j < OB; j++) {
        float m = fmaxf(acc[j], 0.0f);
#pragma unroll
        for (int off = 16; off > 0; off >>= 1)
            m = fmaxf(m, __shfl_xor_sync(FULLMASK, m, off));
        if (lane == 0) {
            int o = obase + j;
            foutp[o] = m;
            doutp[(size_t)o * S_] = m;
        }
    }
}

// ---------------------------------------------------------------------------
// Fused SA layer (+ embedded FPS for the NEXT layer in the first NBATCH
// blocks — fps(n+1) only depends on this layer's centers, so it overlaps).
// ---------------------------------------------------------------------------
template <int NP, int S, int D, int C1, int C2, int C3, int CINp, int PA,
          int NWQ, int SOUT, int NT>
__global__ __launch_bounds__(NT) void k_sa(const float4* __restrict__ xyz4,
                                           const float* __restrict__ pts,
                                           const float4* __restrict__ cxyz,
                                           const float* __restrict__ W1, const float* __restrict__ B1,
                                           const float* __restrict__ W2, const float* __restrict__ B2,
                                           const float* __restrict__ W3, const float* __restrict__ B3,
                                           float* __restrict__ fout,
                                           float* __restrict__ dout, float r2,
                                           float4* __restrict__ nxout,
                                           float* __restrict__ dout2) {
    constexpr int CIN = D + 3;
    extern __shared__ float smdyn[];
    int bid = blockIdx.x;
    int tid = threadIdx.x;
    if constexpr (SOUT > 0) {
        if (bid < NBATCH) {   // embedded FPS for next layer, scheduled first
            fps_soa<S, SOUT, NT>(cxyz, nxout, dout2, bid, tid, smdyn);
            return;
        }
        bid -= NBATCH;
    }

    float* bufA = smdyn;            // [32, PA]
    float* bufB = smdyn + 32 * PA;  // [32, PA]
    float* wsm  = smdyn + 64 * PA;  // [COmax, 20]
    __shared__ int hits[8][32];
    __shared__ int cnts[8];
    __shared__ int nidx[32];
    __shared__ float cen[3];

    int b = bid / S;
    int s = bid - b * S;
    int lane = tid & 31, wd = tid >> 5;

    float4 cv = __ldg(&cxyz[(size_t)b * S + s]);
    float cx = cv.x, cy = cv.y, cz = cv.z, smc = cv.w;
    if (tid == 0) { cen[0] = cx; cen[1] = cy; cen[2] = cz; }

    // ---- ball query: NWQ warps scan disjoint ordered chunks ----
    if (wd < NWQ) {
        constexpr int CHUNK = NP / NWQ;
        const float4* px = xyz4 + (size_t)b * NP;
        int cnt = 0;
        for (int base = wd * CHUNK; base < (wd + 1) * CHUNK; base += 32) {
            int p = base + lane;
            float4 v = __ldg(&px[p]);
            float dot = __fadd_rn(__fadd_rn(__fmul_rn(cx, v.x), __fmul_rn(cy, v.y)),
                                  __fmul_rn(cz, v.z));
            float sq = __fadd_rn(__fadd_rn(smc, v.w), -__fmul_rn(2.0f, dot));
            bool hit = !(sq > r2);
            unsigned m = __ballot_sync(FULLMASK, hit);
            if (hit) {
                int pos = cnt + __popc(m & ((1u << lane) - 1u));
                if (pos < 32) hits[wd][pos] = p;
            }
            cnt += __popc(m);
            if (cnt >= 32) break;
        }
        if (lane == 0) cnts[wd] = (cnt < 32) ? cnt : 32;
    }
    __syncthreads();
    // ---- merge (warp 0), ascending index order; pad with first hit ----
    if (tid < 32) {
        int total = 0;
#pragma unroll
        for (int w2 = 0; w2 < NWQ; w2++) {
            int c = cnts[w2];
            int take = (c < 32 - total) ? c : (32 - total);
            if (lane < take) nidx[total + lane] = hits[w2][lane];
            total += take;
        }
        __syncwarp();
        int i0 = nidx[0];
        if (lane >= total) nidx[lane] = i0;
    }
    __syncthreads();

    // ---- gather: [rel_xyz(3), pts(D), zero-pad] into bufA ----
    float c0 = cen[0], c1 = cen[1], c2 = cen[2];
    for (int e = tid; e < 32 * CINp; e += NT) {
        int k = e / CINp;
        int c = e - k * CINp;
        int p = nidx[k];
        float v = 0.0f;
        if (c < 3) {
            float cc = (c == 0) ? c0 : (c == 1) ? c1 : c2;
            const float* xf = (const float*)(xyz4 + (size_t)b * NP + p);
            v = __fadd_rn(xf[c], -cc);
        } else if (c < CIN) {
            v = pts[((size_t)b * NP + p) * D + (c - 3)];
        }
        bufA[k * PA + c] = v;
    }
    // (stage-1's leading __syncthreads covers gather completion)

    mlp_mid<CIN, CINp, C1, PA, PA, NT>(bufA, bufB, wsm, W1, B1, tid);
    mlp_mid<C1, C1, C2, PA, PA, NT>(bufB, bufA, wsm, W2, B2, tid);
    mlp_last<C2, C2, C3, PA, NT>(bufA, wsm, W3, B3,
                                 fout + ((size_t)b * S + s) * C3,
                                 dout + (size_t)b * C3 * S + s, S, tid);
}

// ---------------------------------------------------------------------------
extern "C" void kernel_launch(void* const* d_in, const int* in_sizes, int n_in,
                              void* d_out, int out_size) {
    const float* xin = (const float*)d_in[0];
    const float* w1a = (const float*)d_in[1];  const float* b1a = (const float*)d_in[2];
    const float* w1b = (const float*)d_in[3];  const float* b1b = (const float*)d_in[4];
    const float* w1c = (const float*)d_in[5];  const float* b1c = (const float*)d_in[6];
    const float* w2a = (const float*)d_in[7];  const float* b2a = (const float*)d_in[8];
    const float* w2b = (const float*)d_in[9];  const float* b2b = (const float*)d_in[10];
    const float* w2c = (const float*)d_in[11]; const float* b2c = (const float*)d_in[12];
    const float* w3a = (const float*)d_in[13]; const float* b3a = (const float*)d_in[14];
    const float* w3b = (const float*)d_in[15]; const float* b3b = (const float*)d_in[16];
    const float* w3c = (const float*)d_in[17]; const float* b3c = (const float*)d_in[18];
    const float* w4a = (const float*)d_in[19]; const float* b4a = (const float*)d_in[20];
    const float* w4b = (const float*)d_in[21]; const float* b4b = (const float*)d_in[22];
    const float* w4c = (const float*)d_in[23]; const float* b4c = (const float*)d_in[24];
    float* out = (float*)d_out;

    float4 *p_xyz0, *p_nx1, *p_nx2, *p_nx3, *p_nx4;
    float *p_pts0, *p_f1, *p_f2, *p_f3, *p_f4;
    cudaGetSymbolAddress((void**)&p_xyz0, g_xyz0);
    cudaGetSymbolAddress((void**)&p_pts0, g_pts0);
    cudaGetSymbolAddress((void**)&p_nx1, g_nx1);
    cudaGetSymbolAddress((void**)&p_f1, g_f1);
    cudaGetSymbolAddress((void**)&p_nx2, g_nx2);
    cudaGetSymbolAddress((void**)&p_f2, g_f2);
    cudaGetSymbolAddress((void**)&p_nx3, g_nx3);
    cudaGetSymbolAddress((void**)&p_f3, g_f3);
    cudaGetSymbolAddress((void**)&p_nx4, g_nx4);
    cudaGetSymbolAddress((void**)&p_f4, g_f4);

    float r2_1 = (float)(0.1 * 0.1);
    float r2_2 = (float)(0.2 * 0.2);
    float r2_3 = (float)(0.4 * 0.4);
    float r2_4 = (float)(0.8 * 0.8);

    // dynamic smem per launch = max(sa usage: 64*PA + COmax*20, fps SoA: 3*S)
    const int SMF1 = 3 * NPTS0 * 4;             // 49152
    const int SM1 = (64 * 36 + 64 * 20) * 4;    // 14336 (fps2 tail: 12288)
    const int SM2 = (64 * 68 + 128 * 20) * 4;   // 27648 (fps3 tail: 3072)
    const int SM3 = (64 * 132 + 256 * 20) * 4;  // 54272 (fps4 tail: 768)
    const int SM4 = (64 * 260 + 512 * 20) * 4;  // 107520

    cudaFuncSetAttribute(k_fps<4096, 1024, 512>,
                         cudaFuncAttributeMaxDynamicSharedMemorySize, SMF1);
    cudaFuncSetAttribute(k_sa<256, 64, 128, 128, 128, 256, 132, 132, 8, 16, 512>,
                         cudaFuncAttributeMaxDynamicSharedMemorySize, SM3);
    cudaFuncSetAttribute(k_sa<64, 16, 256, 256, 256, 512, 260, 260, 2, 0, 512>,
                         cudaFuncAttributeMaxDynamicSharedMemorySize, SM4);

    // stage 0: transpose + output 1
    k_transpose<<<(NBATCH * NPTS0 + 255) / 256, 256>>>(xin, out + O1);

    // fps1 (standalone, packed f32x2)
    k_fps<4096, 1024, 512><<<NBATCH, 512, SMF1>>>(p_xyz0, p_nx1, out + O2);

    // layer 1 SA (+ embedded fps2 -> nx2, out O3)
    k_sa<4096, 1024, 9, 32, 32, 64, 12, 36, 8, 256, 256>
        <<<NBATCH * 1024 + NBATCH, 256, SM1>>>(
        p_xyz0, p_pts0, p_nx1, w1a, b1a, w1b, b1b, w1c, b1c,
        p_f1, out + O6, r2_1, p_nx2, out + O3);

    // layer 2 SA (+ embedded fps3 -> nx3, out O4)
    k_sa<1024, 256, 64, 64, 64, 128, 68, 68, 8, 64, 256>
        <<<NBATCH * 256 + NBATCH, 256, SM2>>>(
        p_nx1, p_f1, p_nx2, w2a, b2a, w2b, b2b, w2c, b2c,
        p_f2, out + O7, r2_2, p_nx3, out + O4);

    // layer 3 SA (+ embedded fps4 -> nx4, out O5), 512 threads
    k_sa<256, 64, 128, 128, 128, 256, 132, 132, 8, 16, 512>
        <<<NBATCH * 64 + NBATCH, 512, SM3>>>(
        p_nx2, p_f2, p_nx3, w3a, b3a, w3b, b3b, w3c, b3c,
        p_f3, out + O8, r2_3, p_nx4, out + O5);

    // layer 4 SA (no tail), 512 threads
    k_sa<64, 16, 256, 256, 256, 512, 260, 260, 2, 0, 512>
        <<<NBATCH * 16, 512, SM4>>>(
        p_nx3, p_f3, p_nx4, w4a, b4a, w4b, b4b, w4c, b4c,
        p_f4, out + O9, r2_4, nullptr, nullptr);
}

// round 7
// speedup vs baseline: 1.3307x; 1.1325x over previous
#include <cuda_runtime.h>

#define NBATCH 16
#define NPTS0  4096
#define FULLMASK 0xffffffffu

// ---------------- device scratch (no allocations allowed) ------------------
__device__ float4 g_xyz0[NBATCH * NPTS0];      // x,y,z,|p|^2
__device__ float  g_pts0[NBATCH * NPTS0 * 9];
__device__ float4 g_nx1[NBATCH * 1024];
__device__ float  g_f1 [NBATCH * 1024 * 64];
__device__ float4 g_nx2[NBATCH * 256];
__device__ float  g_f2 [NBATCH * 256 * 128];
__device__ float4 g_nx3[NBATCH * 64];
__device__ float  g_f3 [NBATCH * 64 * 256];
__device__ float4 g_nx4[NBATCH * 16];
__device__ float  g_f4 [NBATCH * 16 * 512];

// ---------------- d_out offsets (float elements) ----------------------------
#define O1 0        // [16,3,4096]
#define O2 196608   // [16,3,1024]
#define O3 245760   // [16,3,256]
#define O4 258048   // [16,3,64]
#define O5 261120   // [16,3,16]
#define O6 261888   // [16,64,1024]
#define O7 1310464  // [16,128,256]
#define O8 1834752  // [16,256,64]
#define O9 2096896  // [16,512,16]

__device__ __forceinline__ float sq3(float a, float b, float c) {
    return __fadd_rn(__fadd_rn(__fmul_rn(a, a), __fmul_rn(b, b)), __fmul_rn(c, c));
}

// ---------------------------------------------------------------------------
// Transpose [B,9,N] -> point-major scratch (+ |p|^2), emits out1.
// ---------------------------------------------------------------------------
__global__ void k_transpose(const float* __restrict__ in, float* __restrict__ out1) {
    int i = blockIdx.x * blockDim.x + threadIdx.x;
    if (i >= NBATCH * NPTS0) return;
    int b = i >> 12;
    int n = i & (NPTS0 - 1);
    const float* src = in + (size_t)b * 9 * NPTS0;
    float v[9];
#pragma unroll
    for (int c = 0; c < 9; c++) v[c] = src[c * NPTS0 + n];
#pragma unroll
    for (int c = 0; c < 9; c++) g_pts0[(size_t)i * 9 + c] = v[c];
    g_xyz0[i] = make_float4(v[0], v[1], v[2], sq3(v[0], v[1], v[2]));
#pragma unroll
    for (int c = 0; c < 3; c++) out1[((size_t)b * 3 + c) * NPTS0 + n] = v[c];
}

// ---------------------------------------------------------------------------
// FPS body (R4-validated): register-resident coords + float4 smem mirror.
// One barrier per iteration; warp redux.sync argmax -> u64 key in smem ->
// every thread redundantly reduces NW keys.
// ---------------------------------------------------------------------------
template <int NPf, int Sf, int NW>
__device__ void fps_body(const float4* __restrict__ xyz, float4* __restrict__ nx,
                         float* __restrict__ dout, int b, int tid, float4* sc4) {
    constexpr int T = NW * 32;
    constexpr int PPT = (NPf + T - 1) / T;
    constexpr bool GUARD = (NPf % T) != 0;
    __shared__ unsigned long long skey[2][NW];
    int lane = tid & 31, wd = tid >> 5;
    const float4* px = xyz + (size_t)b * NPf;

    float cx[PPT], cy[PPT], cz[PPT], dist[PPT];
#pragma unroll
    for (int j = 0; j < PPT; j++) {
        int p = tid + j * T;
        dist[j] = 1e10f;
        cx[j] = 0.f; cy[j] = 0.f; cz[j] = 0.f;
        if (!GUARD || p < NPf) {
            float4 v = px[p];
            sc4[p] = v;
            cx[j] = v.x; cy[j] = v.y; cz[j] = v.z;
        }
    }
    __syncthreads();

    int far = 0;
    for (int s = 0; s < Sf; s++) {
        float4 f = sc4[far];
        if (tid == 0) {
            nx[(size_t)b * Sf + s] = f;
            dout[((size_t)b * 3 + 0) * Sf + s] = f.x;
            dout[((size_t)b * 3 + 1) * Sf + s] = f.y;
            dout[((size_t)b * 3 + 2) * Sf + s] = f.z;
        }
        unsigned bb = 0u, bi = 0xffffffffu;
#pragma unroll
        for (int j = 0; j < PPT; j++) {
            int p = tid + j * T;
            if (!GUARD || p < NPf) {
                float dx = __fadd_rn(cx[j], -f.x);
                float dy = __fadd_rn(cy[j], -f.y);
                float dz = __fadd_rn(cz[j], -f.z);
                float d = sq3(dx, dy, dz);
                float nd = fminf(dist[j], d);
                dist[j] = nd;
                unsigned nb = __float_as_uint(nd);   // dist >= 0 -> order-preserving
                if (nb > bb || (nb == bb && (unsigned)p < bi)) { bb = nb; bi = (unsigned)p; }
            }
        }
        unsigned mb = __reduce_max_sync(FULLMASK, bb);
        unsigned cand = (bb == mb) ? bi : 0xffffffffu;
        unsigned mi = __reduce_min_sync(FULLMASK, cand);
        if (lane == 0)
            skey[s & 1][wd] = ((unsigned long long)mb << 32) |
                              (unsigned long long)(0xffffffffu - mi);
        __syncthreads();
        unsigned long long best = skey[s & 1][0];
#pragma unroll
        for (int i = 1; i < NW; i++) {
            unsigned long long o = skey[s & 1][i];
            if (o > best) best = o;
        }
        far = (int)(0xffffffffu - (unsigned)(best & 0xffffffffu));
    }
}

template <int NPf, int Sf, int NW>
__global__ __launch_bounds__(NW * 32) void k_fps(const float4* __restrict__ xyz,
                                                 float4* __restrict__ nx,
                                                 float* __restrict__ dout) {
    extern __shared__ float smdyn[];
    fps_body<NPf, Sf, NW>(xyz, nx, dout, blockIdx.x, threadIdx.x, (float4*)smdyn);
}

// ---------------------------------------------------------------------------
// MLP stage (middle), NC centers register-blocked: per g-step load NC f4 +
// OB broadcast w4, issue 4*OB*NC FMAs -> halves smem wavefronts per FMA @NC=2.
// ---------------------------------------------------------------------------
template <int CIa, int CIp, int CO, int PI, int PO, int NC>
__device__ __forceinline__ void mlp_mid(const float* __restrict__ fin,
                                        float* __restrict__ fo,
                                        float* __restrict__ wsm,
                                        const float* __restrict__ W,
                                        const float* __restrict__ Bv, int tid) {
    constexpr int OB = CO / 8;
    int lane = tid & 31;
    int obase = (tid >> 5) * OB;
    float acc[NC][OB];
#pragma unroll
    for (int c = 0; c < NC; c++)
#pragma unroll
        for (int j = 0; j < OB; j++) acc[c][j] = __ldg(Bv + obase + j);
    const float* frow[NC];
#pragma unroll
    for (int c = 0; c < NC; c++) frow[c] = fin + (c * 32 + lane) * PI;

    for (int ci0 = 0; ci0 < CIp; ci0 += 16) {
        __syncthreads();
        for (int e = tid; e < CO * 16; e += 256) {
            int o = e >> 4, g = e & 15;
            int ci = ci0 + g;
            wsm[o * 20 + g] = (ci < CIa) ? __ldg(W + o * CIa + ci) : 0.0f;
        }
        __syncthreads();
        int gmax = (CIp - ci0 < 16) ? (CIp - ci0) : 16;
        for (int g = 0; g < gmax; g += 4) {
            float4 f4[NC];
#pragma unroll
            for (int c = 0; c < NC; c++) f4[c] = *(const float4*)(frow[c] + ci0 + g);
            const float* wb = wsm + obase * 20 + g;
#pragma unroll
            for (int j = 0; j < OB; j++) {
                float4 w4 = *(const float4*)(wb + j * 20);
#pragma unroll
                for (int c = 0; c < NC; c++) {
                    acc[c][j] = fmaf(w4.x, f4[c].x, acc[c][j]);
                    acc[c][j] = fmaf(w4.y, f4[c].y, acc[c][j]);
                    acc[c][j] = fmaf(w4.z, f4[c].z, acc[c][j]);
                    acc[c][j] = fmaf(w4.w, f4[c].w, acc[c][j]);
                }
            }
        }
    }
#pragma unroll
    for (int c = 0; c < NC; c++) {
        float* orow = fo + (c * 32 + lane) * PO + obase;
#pragma unroll
        for (int j = 0; j < OB; j++) orow[j] = fmaxf(acc[c][j], 0.0f);
    }
}

// Last stage: compute, then max over 32 neighbors (lanes) via warp shuffle.
template <int CIa, int CIp, int CO, int PI, int NC>
__device__ __forceinline__ void mlp_last(const float* __restrict__ fin,
                                         float* __restrict__ wsm,
                                         const float* __restrict__ W,
                                         const float* __restrict__ Bv,
                                         float* __restrict__ fout_c0,
                                         float* __restrict__ dout_c0,
                                         int C3sz, int S_, int tid) {
    constexpr int OB = CO / 8;
    int lane = tid & 31;
    int obase = (tid >> 5) * OB;
    float acc[NC][OB];
#pragma unroll
    for (int c = 0; c < NC; c++)
#pragma unroll
        for (int j = 0; j < OB; j++) acc[c][j] = __ldg(Bv + obase + j);
    const float* frow[NC];
#pragma unroll
    for (int c = 0; c < NC; c++) frow[c] = fin + (c * 32 + lane) * PI;

    for (int ci0 = 0; ci0 < CIp; ci0 += 16) {
        __syncthreads();
        for (int e = tid; e < CO * 16; e += 256) {
            int o = e >> 4, g = e & 15;
            int ci = ci0 + g;
            wsm[o * 20 + g] = (ci < CIa) ? __ldg(W + o * CIa + ci) : 0.0f;
        }
        __syncthreads();
        int gmax = (CIp - ci0 < 16) ? (CIp - ci0) : 16;
        for (int g = 0; g < gmax; g += 4) {
            float4 f4[NC];
#pragma unroll
            for (int c = 0; c < NC; c++) f4[c] = *(const float4*)(frow[c] + ci0 + g);
            const float* wb = wsm + obase * 20 + g;
#pragma unroll
            for (int j = 0; j < OB; j++) {
                float4 w4 = *(const float4*)(wb + j * 20);
#pragma unroll
                for (int c = 0; c < NC; c++) {
                    acc[c][j] = fmaf(w4.x, f4[c].x, acc[c][j]);
                    acc[c][j] = fmaf(w4.y, f4[c].y, acc[c][j]);
                    acc[c][j] = fmaf(w4.z, f4[c].z, acc[c][j]);
                    acc[c][j] = fmaf(w4.w, f4[c].w, acc[c][j]);
                }
            }
        }
    }
#pragma unroll
    for (int c = 0; c < NC; c++) {
#pragma unroll
        for (int j = 0; j < OB; j++) {
            float m = fmaxf(acc[c][j], 0.0f);
#pragma unroll
            for (int off = 16; off > 0; off >>= 1)
                m = fmaxf(m, __shfl_xor_sync(FULLMASK, m, off));
            if (lane == 0) {
                int o = obase + j;
                fout_c0[(size_t)c * C3sz + o] = m;
                dout_c0[(size_t)o * S_ + c] = m;
            }
        }
    }
}

// ---------------------------------------------------------------------------
// Fused SA layer, NC centers per block (+ embedded FPS for the NEXT layer in
// the first NBATCH blocks). NWQ = ball-query warps PER CENTER (NC*NWQ <= 8).
// ---------------------------------------------------------------------------
template <int NP, int S, int D, int C1, int C2, int C3, int CINp, int PA,
          int NWQ, int SOUT, int NC>
__global__ __launch_bounds__(256) void k_sa(const float4* __restrict__ xyz4,
                                            const float* __restrict__ pts,
                                            const float4* __restrict__ cxyz,
                                            const float* __restrict__ W1, const float* __restrict__ B1,
                                            const float* __restrict__ W2, const float* __restrict__ B2,
                                            const float* __restrict__ W3, const float* __restrict__ B3,
                                            float* __restrict__ fout,
                                            float* __restrict__ dout, float r2,
                                            float4* __restrict__ nxout,
                                            float* __restrict__ dout2) {
    constexpr int CIN = D + 3;
    extern __shared__ float smdyn[];
    int bid = blockIdx.x;
    int tid = threadIdx.x;
    if constexpr (SOUT > 0) {
        if (bid < NBATCH) {   // embedded FPS for next layer, scheduled first
            fps_body<S, SOUT, 8>(cxyz, nxout, dout2, bid, tid, (float4*)smdyn);
            return;
        }
        bid -= NBATCH;
    }

    float* bufA = smdyn;                 // [NC*32, PA]
    float* bufB = smdyn + NC * 32 * PA;  // [NC*32, PA]
    float* wsm  = smdyn + 2 * NC * 32 * PA;
    __shared__ int hits[8][32];
    __shared__ int cnts[8];
    __shared__ int nidx[NC][32];
    __shared__ float4 cenv[NC];

    constexpr int SG = S / NC;
    int b = bid / SG;
    int s0 = (bid - b * SG) * NC;
    int lane = tid & 31, wd = tid >> 5;

    if (tid < NC) cenv[tid] = __ldg(&cxyz[(size_t)b * S + s0 + tid]);

    // ---- ball query: NC groups of NWQ warps scan disjoint ordered chunks ----
    if (wd < NC * NWQ) {
        int qc = wd / NWQ;
        int qw = wd - qc * NWQ;
        float4 cv = __ldg(&cxyz[(size_t)b * S + s0 + qc]);
        float cx = cv.x, cy = cv.y, cz = cv.z, smc = cv.w;
        constexpr int CHUNK = NP / NWQ;
        const float4* px = xyz4 + (size_t)b * NP;
        int cnt = 0;
        for (int base = qw * CHUNK; base < (qw + 1) * CHUNK; base += 32) {
            int p = base + lane;
            float4 v = __ldg(&px[p]);
            float dot = __fadd_rn(__fadd_rn(__fmul_rn(cx, v.x), __fmul_rn(cy, v.y)),
                                  __fmul_rn(cz, v.z));
            float sq = __fadd_rn(__fadd_rn(smc, v.w), -__fmul_rn(2.0f, dot));
            bool hit = !(sq > r2);
            unsigned m = __ballot_sync(FULLMASK, hit);
            if (hit) {
                int pos = cnt + __popc(m & ((1u << lane) - 1u));
                if (pos < 32) hits[wd][pos] = p;
            }
            cnt += __popc(m);
            if (cnt >= 32) break;
        }
        if (lane == 0) cnts[wd] = (cnt < 32) ? cnt : 32;
    }
    __syncthreads();
    // ---- merge: warp c merges its NWQ chunk lists (ascending index order) ----
    if (wd < NC) {
        int total = 0;
#pragma unroll
        for (int w2 = 0; w2 < NWQ; w2++) {
            int c = cnts[wd * NWQ + w2];
            int take = (c < 32 - total) ? c : (32 - total);
            if (lane < take) nidx[wd][total + lane] = hits[wd * NWQ + w2][lane];
            total += take;
        }
        __syncwarp();
        int i0 = nidx[wd][0];
        if (lane >= total) nidx[wd][lane] = i0;
    }
    __syncthreads();

    // ---- gather: [rel_xyz(3), pts(D), zero-pad] into bufA rows ----
    for (int e = tid; e < NC * 32 * CINp; e += 256) {
        int kk = e / CINp;
        int c = e - kk * CINp;
        int cc = kk >> 5;
        int p = nidx[cc][kk & 31];
        float v = 0.0f;
        if (c < 3) {
            float4 cv = cenv[cc];
            float ccf = (c == 0) ? cv.x : (c == 1) ? cv.y : cv.z;
            const float* xf = (const float*)(xyz4 + (size_t)b * NP + p);
            v = __fadd_rn(xf[c], -ccf);
        } else if (c < CIN) {
            v = pts[((size_t)b * NP + p) * D + (c - 3)];
        }
        bufA[kk * PA + c] = v;
    }
    // (stage-1's leading __syncthreads covers gather completion)

    mlp_mid<CIN, CINp, C1, PA, PA, NC>(bufA, bufB, wsm, W1, B1, tid);
    mlp_mid<C1, C1, C2, PA, PA, NC>(bufB, bufA, wsm, W2, B2, tid);
    mlp_last<C2, C2, C3, PA, NC>(bufA, wsm, W3, B3,
                                 fout + ((size_t)b * S + s0) * C3,
                                 dout + (size_t)b * C3 * S + s0, C3, S, tid);
}

// ---------------------------------------------------------------------------
extern "C" void kernel_launch(void* const* d_in, const int* in_sizes, int n_in,
                              void* d_out, int out_size) {
    const float* xin = (const float*)d_in[0];
    const float* w1a = (const float*)d_in[1];  const float* b1a = (const float*)d_in[2];
    const float* w1b = (const float*)d_in[3];  const float* b1b = (const float*)d_in[4];
    const float* w1c = (const float*)d_in[5];  const float* b1c = (const float*)d_in[6];
    const float* w2a = (const float*)d_in[7];  const float* b2a = (const float*)d_in[8];
    const float* w2b = (const float*)d_in[9];  const float* b2b = (const float*)d_in[10];
    const float* w2c = (const float*)d_in[11]; const float* b2c = (const float*)d_in[12];
    const float* w3a = (const float*)d_in[13]; const float* b3a = (const float*)d_in[14];
    const float* w3b = (const float*)d_in[15]; const float* b3b = (const float*)d_in[16];
    const float* w3c = (const float*)d_in[17]; const float* b3c = (const float*)d_in[18];
    const float* w4a = (const float*)d_in[19]; const float* b4a = (const float*)d_in[20];
    const float* w4b = (const float*)d_in[21]; const float* b4b = (const float*)d_in[22];
    const float* w4c = (const float*)d_in[23]; const float* b4c = (const float*)d_in[24];
    float* out = (float*)d_out;

    float4 *p_xyz0, *p_nx1, *p_nx2, *p_nx3, *p_nx4;
    float *p_pts0, *p_f1, *p_f2, *p_f3, *p_f4;
    cudaGetSymbolAddress((void**)&p_xyz0, g_xyz0);
    cudaGetSymbolAddress((void**)&p_pts0, g_pts0);
    cudaGetSymbolAddress((void**)&p_nx1, g_nx1);
    cudaGetSymbolAddress((void**)&p_f1, g_f1);
    cudaGetSymbolAddress((void**)&p_nx2, g_nx2);
    cudaGetSymbolAddress((void**)&p_f2, g_f2);
    cudaGetSymbolAddress((void**)&p_nx3, g_nx3);
    cudaGetSymbolAddress((void**)&p_f3, g_f3);
    cudaGetSymbolAddress((void**)&p_nx4, g_nx4);
    cudaGetSymbolAddress((void**)&p_f4, g_f4);

    float r2_1 = (float)(0.1 * 0.1);
    float r2_2 = (float)(0.2 * 0.2);
    float r2_3 = (float)(0.4 * 0.4);
    float r2_4 = (float)(0.8 * 0.8);

    // dynamic smem = max(sa usage: 2*NC*32*PA + COmax*20 floats, fps tail: S*16B)
    const int SMF1 = NPTS0 * 16;                        // 65536 (fps1 float4 mirror)
    const int SM1 = (128 * 36 + 64 * 20) * 4;           // 23552 (fps2 tail: 16384)
    const int SM2 = (128 * 68 + 128 * 20) * 4;          // 45056 (fps3 tail: 4096)
    const int SM3 = (64 * 132 + 256 * 20) * 4;          // 54272 (fps4 tail: 1024)
    const int SM4 = (64 * 260 + 512 * 20) * 4;          // 107520

    cudaFuncSetAttribute(k_fps<4096, 1024, 16>,
                         cudaFuncAttributeMaxDynamicSharedMemorySize, SMF1);
    cudaFuncSetAttribute(k_sa<256, 64, 128, 128, 128, 256, 132, 132, 8, 16, 1>,
                         cudaFuncAttributeMaxDynamicSharedMemorySize, SM3);
    cudaFuncSetAttribute(k_sa<64, 16, 256, 256, 256, 512, 260, 260, 2, 0, 1>,
                         cudaFuncAttributeMaxDynamicSharedMemorySize, SM4);

    // stage 0: transpose + output 1
    k_transpose<<<(NBATCH * NPTS0 + 255) / 256, 256>>>(xin, out + O1);

    // fps1 (standalone, register-resident body)
    k_fps<4096, 1024, 16><<<NBATCH, 512, SMF1>>>(p_xyz0, p_nx1, out + O2);

    // layer 1 SA, NC=2 (+ embedded fps2 -> nx2, out O3)
    k_sa<4096, 1024, 9, 32, 32, 64, 12, 36, 4, 256, 2>
        <<<NBATCH * 512 + NBATCH, 256, SM1>>>(
        p_xyz0, p_pts0, p_nx1, w1a, b1a, w1b, b1b, w1c, b1c,
        p_f1, out + O6, r2_1, p_nx2, out + O3);

    // layer 2 SA, NC=2 (+ embedded fps3 -> nx3, out O4)
    k_sa<1024, 256, 64, 64, 64, 128, 68, 68, 4, 64, 2>
        <<<NBATCH * 128 + NBATCH, 256, SM2>>>(
        p_nx1, p_f1, p_nx2, w2a, b2a, w2b, b2b, w2c, b2c,
        p_f2, out + O7, r2_2, p_nx3, out + O4);

    // layer 3 SA, NC=1 (+ embedded fps4 -> nx4, out O5)
    k_sa<256, 64, 128, 128, 128, 256, 132, 132, 8, 16, 1>
        <<<NBATCH * 64 + NBATCH, 256, SM3>>>(
        p_nx2, p_f2, p_nx3, w3a, b3a, w3b, b3b, w3c, b3c,
        p_f3, out + O8, r2_3, p_nx4, out + O5);

    // layer 4 SA, NC=1 (no tail)
    k_sa<64, 16, 256, 256, 256, 512, 260, 260, 2, 0, 1>
        <<<NBATCH * 16, 256, SM4>>>(
        p_nx3, p_f3, p_nx4, w4a, b4a, w4b, b4b, w4c, b4c,
        p_f4, out + O9, r2_4, nullptr, nullptr);
}